// round 4
// baseline (speedup 1.0000x reference)
#include <cuda_runtime.h>
#include <cstdint>
#include <stdint.h>
#include <math.h>

#define DEPTH 15
#define N_NODES ((1 << DEPTH) - 1)   // 32767
#define DD 512
#define HH 512
#define G4 (4 * HH)                  // 2048 gate columns, packed order [i | o | u | f]

// ---------------- scratch (device globals; allocation-free) ----------------
__device__ float g_P[(size_t)N_NODES * G4];              // x-part + bias, all gates (268 MB)
__device__ float g_Giou[(size_t)(1 << (DEPTH - 2)) * 3 * HH]; // parent-indexed iou h-part (50 MB)
__device__ float g_Gf[(size_t)(1 << (DEPTH - 1)) * HH];  // child-indexed f h-part (33 MB)
__device__ float g_h[(size_t)N_NODES * HH];
__device__ float g_c[(size_t)N_NODES * HH];
__device__ float g_Wx[(size_t)G4 * DD];                  // [i|o|u|f] x-cols (tf32-rounded)
__device__ float g_Wh[(size_t)G4 * HH];                  // [i|o|u|f] h-cols (tf32-rounded)
__device__ float g_b[G4];                                // [i|o|u|f]

// ---------------- fast activations ----------------
__device__ __forceinline__ float tanh_fast(float x) {
    float y;
    asm("tanh.approx.f32 %0, %1;" : "=f"(y) : "f"(x));
    return y;
}
__device__ __forceinline__ float sig_fast(float x) {
    return 0.5f * tanh_fast(0.5f * x) + 0.5f;
}
__device__ __forceinline__ float to_tf32(float x) {
    unsigned int r;
    asm("cvt.rna.tf32.f32 %0, %1;" : "=r"(r) : "f"(x));
    return __uint_as_float(r);
}

// ---------------- pack weights, order [i|o|u|f] ----------------
__global__ void pack_weights(const float* __restrict__ Wi, const float* __restrict__ bi,
                             const float* __restrict__ Wf, const float* __restrict__ bf,
                             const float* __restrict__ Wo, const float* __restrict__ bo,
                             const float* __restrict__ Wu, const float* __restrict__ bu) {
    int idx = blockIdx.x * blockDim.x + threadIdx.x;
    if (idx < G4 * DD) {
        int row = idx >> 9;        // 0..2047
        int col = idx & 511;
        int r = row & 511;
        int g = row >> 9;          // 0=i,1=o,2=u,3=f
        const float* W = (g == 0) ? Wi : (g == 1) ? Wo : (g == 2) ? Wu : Wf;
        const float* src = W + (size_t)r * (DD + HH);
        g_Wx[idx] = to_tf32(src[col]);
        g_Wh[idx] = to_tf32(src[DD + col]);
    }
    if (idx < G4) {
        int g = idx >> 9, r = idx & 511;
        const float* b = (g == 0) ? bi : (g == 1) ? bo : (g == 2) ? bu : bf;
        g_b[idx] = b[r];
    }
}

// ---------------- tf32 tensor-core GEMM ----------------
// C(M x N) = A(M x 512) @ W(N x 512)^T (+bias), N multiple of 128
// BM x 128 x 32 block tile, 8 warps, warp tile 64 x (128*64/BM)
// PAIR_SUM: logical A row r = Araw[2r] + Araw[2r+1] (rows of 512)
#define SM_STRIDE 36

template <int BM, bool PAIR_SUM, bool ADD_BIAS>
__global__ __launch_bounds__(256, 1) void gemm_tc2(const float* __restrict__ A,
                                                   const float* __restrict__ W,
                                                   float* __restrict__ C,
                                                   int M, int N, int bias_off) {
    constexpr int WARPS_N = (BM == 256) ? 2 : 4;  // warp grid: (8/WARPS_N) x WARPS_N
    constexpr int WN_SPAN = 128 / WARPS_N;        // 64 or 32
    constexpr int WNT = WN_SPAN / 8;              // 8 or 4 n-tiles per warp
    constexpr int A_ITERS = BM / 32;              // float4 loads per thread for A slab

    extern __shared__ float smem[];
    float* As = smem;                    // BM x SM_STRIDE
    float* Ws = smem + BM * SM_STRIDE;   // 128 x SM_STRIDE

    const int bm = blockIdx.y * BM;
    const int bn = blockIdx.x * 128;
    const int tid = threadIdx.x;
    const int lane = tid & 31;
    const int wid = tid >> 5;
    const int wm = (wid / WARPS_N) * 64;
    const int wn = (wid % WARPS_N) * WN_SPAN;
    const int g = lane >> 2;
    const int tig = lane & 3;

    float acc[4][WNT][4];
#pragma unroll
    for (int mt = 0; mt < 4; mt++)
#pragma unroll
        for (int nt = 0; nt < WNT; nt++)
#pragma unroll
            for (int r = 0; r < 4; r++) acc[mt][nt][r] = 0.f;

    for (int k0 = 0; k0 < DD; k0 += 32) {
        // A slab: BM x 32 floats = BM*8 float4, 256 threads
#pragma unroll
        for (int i = 0; i < A_ITERS; i++) {
            int id = tid + i * 256;
            int row = id >> 3;
            int kq = (id & 7) << 2;
            float4 v = make_float4(0.f, 0.f, 0.f, 0.f);
            if (bm + row < M) {
                if (PAIR_SUM) {
                    const float* p0 = A + (size_t)(2 * (bm + row)) * DD + k0 + kq;
                    float4 a0 = *(const float4*)p0;
                    float4 a1 = *(const float4*)(p0 + DD);
                    v.x = a0.x + a1.x; v.y = a0.y + a1.y;
                    v.z = a0.z + a1.z; v.w = a0.w + a1.w;
                } else {
                    v = *(const float4*)(A + (size_t)(bm + row) * DD + k0 + kq);
                }
                v.x = to_tf32(v.x); v.y = to_tf32(v.y);
                v.z = to_tf32(v.z); v.w = to_tf32(v.w);
            }
            *(float4*)(As + row * SM_STRIDE + kq) = v;
        }
        // W slab: 128 x 32 floats (pre-rounded at pack)
#pragma unroll
        for (int i = 0; i < 4; i++) {
            int id = tid + i * 256;
            int row = id >> 3;
            int kq = (id & 7) << 2;
            float4 w = *(const float4*)(W + (size_t)(bn + row) * DD + k0 + kq);
            *(float4*)(Ws + row * SM_STRIDE + kq) = w;
        }
        __syncthreads();

#pragma unroll
        for (int ks = 0; ks < 4; ks++) {
            const int kk = ks << 3;
            unsigned int a[4][4];
#pragma unroll
            for (int mt = 0; mt < 4; mt++) {
                int m = wm + (mt << 4) + g;
                a[mt][0] = __float_as_uint(As[m * SM_STRIDE + kk + tig]);
                a[mt][1] = __float_as_uint(As[(m + 8) * SM_STRIDE + kk + tig]);
                a[mt][2] = __float_as_uint(As[m * SM_STRIDE + kk + tig + 4]);
                a[mt][3] = __float_as_uint(As[(m + 8) * SM_STRIDE + kk + tig + 4]);
            }
            unsigned int b[WNT][2];
#pragma unroll
            for (int nt = 0; nt < WNT; nt++) {
                int n = wn + (nt << 3) + g;
                b[nt][0] = __float_as_uint(Ws[n * SM_STRIDE + kk + tig]);
                b[nt][1] = __float_as_uint(Ws[n * SM_STRIDE + kk + tig + 4]);
            }
#pragma unroll
            for (int mt = 0; mt < 4; mt++)
#pragma unroll
                for (int nt = 0; nt < WNT; nt++) {
                    float* c = acc[mt][nt];
                    asm volatile(
                        "mma.sync.aligned.m16n8k8.row.col.f32.tf32.tf32.f32 "
                        "{%0,%1,%2,%3}, {%4,%5,%6,%7}, {%8,%9}, {%0,%1,%2,%3};"
                        : "+f"(c[0]), "+f"(c[1]), "+f"(c[2]), "+f"(c[3])
                        : "r"(a[mt][0]), "r"(a[mt][1]), "r"(a[mt][2]), "r"(a[mt][3]),
                          "r"(b[nt][0]), "r"(b[nt][1]));
                }
        }
        __syncthreads();
    }

#pragma unroll
    for (int mt = 0; mt < 4; mt++) {
        int row0 = bm + wm + (mt << 4) + g;
#pragma unroll
        for (int nt = 0; nt < WNT; nt++) {
            int col = bn + wn + (nt << 3) + (tig << 1);
            float b0 = 0.f, b1 = 0.f;
            if (ADD_BIAS) { b0 = g_b[bias_off + col]; b1 = g_b[bias_off + col + 1]; }
            if (row0 < M) {
                C[(size_t)row0 * N + col]     = acc[mt][nt][0] + b0;
                C[(size_t)row0 * N + col + 1] = acc[mt][nt][1] + b1;
            }
            if (row0 + 8 < M) {
                C[(size_t)(row0 + 8) * N + col]     = acc[mt][nt][2] + b0;
                C[(size_t)(row0 + 8) * N + col + 1] = acc[mt][nt][3] + b1;
            }
        }
    }
}

// ---------------- leaf level (h = 0 children), float4 ----------------
__global__ void leaf_kernel(int start, int cnt) {
    int idx = blockIdx.x * blockDim.x + threadIdx.x;
    if (idx >= cnt * (HH / 4)) return;
    int b = idx >> 7, j4 = (idx & 127) << 2;
    size_t n = (size_t)(start + b);
    const float* Pp = g_P + n * G4;
    float4 pi = *(const float4*)(Pp + j4);
    float4 po = *(const float4*)(Pp + HH + j4);
    float4 pu = *(const float4*)(Pp + 2 * HH + j4);
    float4 c, h;
    {
        float i0 = sig_fast(pi.x), o0 = sig_fast(po.x), u0 = tanh_fast(pu.x);
        c.x = i0 * u0; h.x = o0 * tanh_fast(c.x);
        float i1 = sig_fast(pi.y), o1 = sig_fast(po.y), u1 = tanh_fast(pu.y);
        c.y = i1 * u1; h.y = o1 * tanh_fast(c.y);
        float i2 = sig_fast(pi.z), o2 = sig_fast(po.z), u2 = tanh_fast(pu.z);
        c.z = i2 * u2; h.z = o2 * tanh_fast(c.z);
        float i3 = sig_fast(pi.w), o3 = sig_fast(po.w), u3 = tanh_fast(pu.w);
        c.w = i3 * u3; h.w = o3 * tanh_fast(c.w);
    }
    *(float4*)(g_c + n * HH + j4) = c;
    *(float4*)(g_h + n * HH + j4) = h;
}

// ---------------- internal level combine, float4 ----------------
__global__ void combine_kernel(int start, int cnt, int cs) {
    int idx = blockIdx.x * blockDim.x + threadIdx.x;
    if (idx >= cnt * (HH / 4)) return;
    int b = idx >> 7, j4 = (idx & 127) << 2;
    size_t n = (size_t)(start + b);
    const float* Pp = g_P + n * G4;
    const float* Gi = g_Giou + (size_t)b * (3 * HH);
    float4 pi = *(const float4*)(Pp + j4);
    float4 po = *(const float4*)(Pp + HH + j4);
    float4 pu = *(const float4*)(Pp + 2 * HH + j4);
    float4 pf = *(const float4*)(Pp + 3 * HH + j4);
    float4 gi = *(const float4*)(Gi + j4);
    float4 go = *(const float4*)(Gi + HH + j4);
    float4 gu = *(const float4*)(Gi + 2 * HH + j4);
    float4 gfl = *(const float4*)(g_Gf + (size_t)(2 * b) * HH + j4);
    float4 gfr = *(const float4*)(g_Gf + (size_t)(2 * b + 1) * HH + j4);
    float4 cl = *(const float4*)(g_c + (size_t)(cs + 2 * b) * HH + j4);
    float4 cr = *(const float4*)(g_c + (size_t)(cs + 2 * b + 1) * HH + j4);
    float4 c, h;
#define COMB(X)                                                          \
    {                                                                    \
        float i_ = sig_fast(pi.X + gi.X);                                \
        float o_ = sig_fast(po.X + go.X);                                \
        float u_ = tanh_fast(pu.X + gu.X);                               \
        float fl_ = sig_fast(pf.X + gfl.X);                              \
        float fr_ = sig_fast(pf.X + gfr.X);                              \
        c.X = i_ * u_ + fl_ * cl.X + fr_ * cr.X;                         \
        h.X = o_ * tanh_fast(c.X);                                       \
    }
    COMB(x) COMB(y) COMB(z) COMB(w)
#undef COMB
    *(float4*)(g_c + n * HH + j4) = c;
    *(float4*)(g_h + n * HH + j4) = h;
}

// ---------------- output: [h[0] | c[0]] ----------------
__global__ void write_out(float* __restrict__ out, int out_size) {
    int j = blockIdx.x * blockDim.x + threadIdx.x;
    if (j < HH && j < out_size) out[j] = g_h[j];
    int j2 = j + HH;
    if (j < HH && j2 < out_size) out[j2] = g_c[j];
}

extern "C" void kernel_launch(void* const* d_in, const int* in_sizes, int n_in,
                              void* d_out, int out_size) {
    const float* x  = (const float*)d_in[0];
    const float* Wi = (const float*)d_in[1];
    const float* bi = (const float*)d_in[2];
    const float* Wf = (const float*)d_in[3];
    const float* bf = (const float*)d_in[4];
    const float* Wo = (const float*)d_in[5];
    const float* bo = (const float*)d_in[6];
    const float* Wu = (const float*)d_in[7];
    const float* bu = (const float*)d_in[8];
    float* out = (float*)d_out;

    float *pP, *pGiou, *pGf, *ph, *pWx, *pWh;
    cudaGetSymbolAddress((void**)&pP,    g_P);
    cudaGetSymbolAddress((void**)&pGiou, g_Giou);
    cudaGetSymbolAddress((void**)&pGf,   g_Gf);
    cudaGetSymbolAddress((void**)&ph,    g_h);
    cudaGetSymbolAddress((void**)&pWx,   g_Wx);
    cudaGetSymbolAddress((void**)&pWh,   g_Wh);

    const int SMEM_256 = (256 + 128) * SM_STRIDE * 4;  // 55.3 KB
    const int SMEM_128 = (128 + 128) * SM_STRIDE * 4;  // 36.9 KB
    cudaFuncSetAttribute(gemm_tc2<256, false, true>,
                         cudaFuncAttributeMaxDynamicSharedMemorySize, SMEM_256);
    cudaFuncSetAttribute(gemm_tc2<256, true, false>,
                         cudaFuncAttributeMaxDynamicSharedMemorySize, SMEM_256);
    cudaFuncSetAttribute(gemm_tc2<256, false, false>,
                         cudaFuncAttributeMaxDynamicSharedMemorySize, SMEM_256);
    cudaFuncSetAttribute(gemm_tc2<128, true, false>,
                         cudaFuncAttributeMaxDynamicSharedMemorySize, SMEM_128);
    cudaFuncSetAttribute(gemm_tc2<128, false, false>,
                         cudaFuncAttributeMaxDynamicSharedMemorySize, SMEM_128);

    pack_weights<<<(G4 * DD + 255) / 256, 256>>>(Wi, bi, Wf, bf, Wo, bo, Wu, bu);

    // P = x @ Wx^T + b, all nodes
    {
        dim3 grid(G4 / 128, (N_NODES + 255) / 256);
        gemm_tc2<256, false, true><<<grid, 256, SMEM_256>>>(x, pWx, pP, N_NODES, G4, 0);
    }

    // leaves
    {
        int start = (1 << (DEPTH - 1)) - 1;
        int cnt = 1 << (DEPTH - 1);
        leaf_kernel<<<(cnt * (HH / 4) + 255) / 256, 256>>>(start, cnt);
    }

    // internal levels
    for (int lvl = DEPTH - 2; lvl >= 0; lvl--) {
        int start = (1 << lvl) - 1;
        int cnt = 1 << lvl;
        int cs = 2 * start + 1;
        const float* hchild = ph + (size_t)cs * HH;

        // iou gates on pair-summed h: M=cnt, N=1536
        if (cnt >= 2048) {
            dim3 grid(1536 / 128, (cnt + 255) / 256);
            gemm_tc2<256, true, false><<<grid, 256, SMEM_256>>>(hchild, pWh, pGiou, cnt, 1536, 0);
        } else {
            dim3 grid(1536 / 128, (cnt + 127) / 128);
            gemm_tc2<128, true, false><<<grid, 256, SMEM_128>>>(hchild, pWh, pGiou, cnt, 1536, 0);
        }
        // f gate on raw children: M=2*cnt, N=512
        int Mf = 2 * cnt;
        const float* Wf_h = pWh + (size_t)(3 * HH) * DD;
        if (Mf >= 2048) {
            dim3 grid(512 / 128, (Mf + 255) / 256);
            gemm_tc2<256, false, false><<<grid, 256, SMEM_256>>>(hchild, Wf_h, pGf, Mf, 512, 0);
        } else {
            dim3 grid(512 / 128, (Mf + 127) / 128);
            gemm_tc2<128, false, false><<<grid, 256, SMEM_128>>>(hchild, Wf_h, pGf, Mf, 512, 0);
        }
        combine_kernel<<<(cnt * (HH / 4) + 255) / 256, 256>>>(start, cnt, cs);
    }

    write_out<<<(2 * HH + 255) / 256, 256>>>(out, out_size);
}